// round 1
// baseline (speedup 1.0000x reference)
#include <cuda_runtime.h>
#include <math.h>

#define N_  50000
#define T_  25
#define A_  16
#define H_  128
#define I_  64
#define E_  800000
#define G3_ 384   // 3*H
#define K_  144   // H + A

// Scratch (no allocations allowed): device globals.
__device__ float g_xln[N_ * H_];     // layernormed + src-norm-scaled features
__device__ float g_agg[N_ * H_];     // scatter-add accumulator
__device__ float g_deg_out[N_];
__device__ float g_deg_in[N_];

__device__ __forceinline__ float softplusf(float x) {
    return x > 0.f ? x + log1pf(expf(-x)) : log1pf(expf(x));
}

// ---------------------------------------------------------------------------
// GRU: 16 rows per block, all 25 steps in-block. W (transposed k-major) and the
// [h | x_t] tile live in smem. Thread tile: 4 rows x 2 cols x {r,z,hn,in}.
// smem = 144*384*4 + 16*144*4 = 230400 bytes.
// ---------------------------------------------------------------------------
__global__ void __launch_bounds__(256, 1) gru_kernel(
    const float* __restrict__ actions,  // (N, T, A)
    const float* __restrict__ hidden,   // (1, N, H)
    const float* __restrict__ W_ih,     // (3H, A)
    const float* __restrict__ W_hh,     // (3H, H)
    const float* __restrict__ b_ih,     // (3H)
    const float* __restrict__ b_hh,     // (3H)
    float* __restrict__ h_out)          // (N, H) -> d_out tail region
{
    extern __shared__ float sm[];
    float* Ws = sm;               // [K_][G3_]  (k-major transposed weights)
    float* hx = sm + K_ * G3_;    // [16][K_]   (h in cols 0..127, x in 128..143)

    const int tid   = threadIdx.x;
    const int rowg  = tid >> 6;        // 0..3  (constant within a warp)
    const int l2    = tid & 63;        // 0..63
    const int c0    = l2 << 1;         // column base, 0..126 (even)
    const int r0    = rowg << 2;       // local row base
    const int grow0 = blockIdx.x << 4; // global row base (16 rows/block)

    // Stage W_hh: [g][k] -> Ws[k][g], k in [0,128)
    for (int idx = tid; idx < G3_ * (H_ / 4); idx += 256) {
        int g  = idx >> 5;
        int k  = (idx & 31) << 2;
        float4 w = __ldg(reinterpret_cast<const float4*>(W_hh) + idx);
        Ws[(k + 0) * G3_ + g] = w.x;
        Ws[(k + 1) * G3_ + g] = w.y;
        Ws[(k + 2) * G3_ + g] = w.z;
        Ws[(k + 3) * G3_ + g] = w.w;
    }
    // Stage W_ih: [g][a] -> Ws[128+a][g]
    for (int idx = tid; idx < G3_ * (A_ / 4); idx += 256) {
        int g = idx >> 2;
        int k = 128 + ((idx & 3) << 2);
        float4 w = __ldg(reinterpret_cast<const float4*>(W_ih) + idx);
        Ws[(k + 0) * G3_ + g] = w.x;
        Ws[(k + 1) * G3_ + g] = w.y;
        Ws[(k + 2) * G3_ + g] = w.z;
        Ws[(k + 3) * G3_ + g] = w.w;
    }
    // Stage h0
    for (int idx = tid; idx < 16 * (H_ / 4); idx += 256) {
        int r  = idx >> 5;
        int k4 = idx & 31;
        float4 v = __ldg(reinterpret_cast<const float4*>(hidden + (grow0 + r) * H_) + k4);
        *reinterpret_cast<float4*>(&hx[r * K_ + (k4 << 2)]) = v;
    }
    // Biases for this thread's two columns (gate order r,z,n)
    float br0 = __ldg(b_ih + c0)       + __ldg(b_hh + c0);
    float br1 = __ldg(b_ih + c0 + 1)   + __ldg(b_hh + c0 + 1);
    float bz0 = __ldg(b_ih + 128 + c0)     + __ldg(b_hh + 128 + c0);
    float bz1 = __ldg(b_ih + 128 + c0 + 1) + __ldg(b_hh + 128 + c0 + 1);
    float bi0 = __ldg(b_ih + 256 + c0);
    float bi1 = __ldg(b_ih + 256 + c0 + 1);
    float bh0 = __ldg(b_hh + 256 + c0);
    float bh1 = __ldg(b_hh + 256 + c0 + 1);
    __syncthreads();

    const float* act_base = actions + (long long)grow0 * (T_ * A_);

    for (int t = 0; t < T_; ++t) {
        // load x_t tile (16 rows x 16) into hx[.][128..143]
        {
            int r = tid >> 4, a = tid & 15;
            hx[r * K_ + 128 + a] = __ldg(act_base + r * (T_ * A_) + t * A_ + a);
        }
        __syncthreads();

        float ar[4][2], az[4][2], ahn[4][2], ain[4][2];
        #pragma unroll
        for (int m = 0; m < 4; ++m) {
            ar[m][0] = br0;  ar[m][1] = br1;
            az[m][0] = bz0;  az[m][1] = bz1;
            ahn[m][0] = bh0; ahn[m][1] = bh1;
            ain[m][0] = bi0; ain[m][1] = bi1;
        }

        // recurrent part: k in [0,128)
        #pragma unroll 4
        for (int k = 0; k < 128; ++k) {
            float2 wr = *reinterpret_cast<const float2*>(&Ws[k * G3_ + c0]);
            float2 wz = *reinterpret_cast<const float2*>(&Ws[k * G3_ + 128 + c0]);
            float2 wn = *reinterpret_cast<const float2*>(&Ws[k * G3_ + 256 + c0]);
            #pragma unroll
            for (int m = 0; m < 4; ++m) {
                float h = hx[(r0 + m) * K_ + k];
                ar[m][0]  += h * wr.x;  ar[m][1]  += h * wr.y;
                az[m][0]  += h * wz.x;  az[m][1]  += h * wz.y;
                ahn[m][0] += h * wn.x;  ahn[m][1] += h * wn.y;
            }
        }
        // input part: k in [128,144) -> r,z merged; n goes to ain (separate!)
        #pragma unroll
        for (int k = 128; k < 144; ++k) {
            float2 wr = *reinterpret_cast<const float2*>(&Ws[k * G3_ + c0]);
            float2 wz = *reinterpret_cast<const float2*>(&Ws[k * G3_ + 128 + c0]);
            float2 wn = *reinterpret_cast<const float2*>(&Ws[k * G3_ + 256 + c0]);
            #pragma unroll
            for (int m = 0; m < 4; ++m) {
                float xv = hx[(r0 + m) * K_ + k];
                ar[m][0]  += xv * wr.x;  ar[m][1]  += xv * wr.y;
                az[m][0]  += xv * wz.x;  az[m][1]  += xv * wz.y;
                ain[m][0] += xv * wn.x;  ain[m][1] += xv * wn.y;
            }
        }

        // read h_old (before anyone overwrites), then sync, then write h_new
        float hold[4][2];
        #pragma unroll
        for (int m = 0; m < 4; ++m) {
            hold[m][0] = hx[(r0 + m) * K_ + c0];
            hold[m][1] = hx[(r0 + m) * K_ + c0 + 1];
        }
        __syncthreads();

        #pragma unroll
        for (int m = 0; m < 4; ++m) {
            #pragma unroll
            for (int jc = 0; jc < 2; ++jc) {
                float r = 1.f / (1.f + expf(-ar[m][jc]));
                float z = 1.f / (1.f + expf(-az[m][jc]));
                float n = tanhf(ain[m][jc] + r * ahn[m][jc]);
                float hnew = (1.f - z) * n + z * hold[m][jc];
                if (t == T_ - 1)
                    h_out[(grow0 + r0 + m) * H_ + c0 + jc] = hnew;
                else
                    hx[(r0 + m) * K_ + c0 + jc] = hnew;
            }
        }
        // next iteration's __syncthreads (after x load) orders hnew writes
    }
}

// ---------------------------------------------------------------------------
// LayerNorm + scale by src-norm (deg_out^-0.5). One warp per row.
// ---------------------------------------------------------------------------
__global__ void __launch_bounds__(256) ln_scale_kernel(
    const float* __restrict__ h, const float* __restrict__ ln_g,
    const float* __restrict__ ln_b)
{
    int row  = (blockIdx.x << 3) + (threadIdx.x >> 5);
    int lane = threadIdx.x & 31;
    float4 v = __ldg(reinterpret_cast<const float4*>(h + row * H_) + lane);
    float s  = v.x + v.y + v.z + v.w;
    float ss = v.x * v.x + v.y * v.y + v.z * v.z + v.w * v.w;
    #pragma unroll
    for (int o = 16; o > 0; o >>= 1) {
        s  += __shfl_xor_sync(0xffffffffu, s, o);
        ss += __shfl_xor_sync(0xffffffffu, ss, o);
    }
    float mu  = s * (1.f / 128.f);
    float var = ss * (1.f / 128.f) - mu * mu;
    float inv = rsqrtf(var + 1e-5f);
    float dg  = g_deg_out[row];
    float ns  = dg > 0.f ? rsqrtf(dg) : 1.f;
    float4 g4 = __ldg(reinterpret_cast<const float4*>(ln_g) + lane);
    float4 b4 = __ldg(reinterpret_cast<const float4*>(ln_b) + lane);
    float4 o4;
    o4.x = ((v.x - mu) * inv * g4.x + b4.x) * ns;
    o4.y = ((v.y - mu) * inv * g4.y + b4.y) * ns;
    o4.z = ((v.z - mu) * inv * g4.z + b4.z) * ns;
    o4.w = ((v.w - mu) * inv * g4.w + b4.w) * ns;
    *reinterpret_cast<float4*>(g_xln + row * H_ + (lane << 2)) = o4;
}

__global__ void zero_deg_kernel() {
    int i = blockIdx.x * 256 + threadIdx.x;
    if (i < N_) { g_deg_in[i] = 0.f; g_deg_out[i] = 0.f; }
}

__global__ void zero_agg_kernel() {
    int i = blockIdx.x * 256 + threadIdx.x;   // N_*H_/4 = 1,600,000 exact
    reinterpret_cast<float4*>(g_agg)[i] = make_float4(0.f, 0.f, 0.f, 0.f);
}

__global__ void degree_kernel(const int* __restrict__ src, const int* __restrict__ dst) {
    int e = blockIdx.x * 256 + threadIdx.x;   // grid exact: E_/256
    atomicAdd(&g_deg_out[__ldg(src + e)], 1.f);
    atomicAdd(&g_deg_in[__ldg(dst + e)], 1.f);
}

// One warp per edge; lane handles a float4 column chunk. float4 atomics (sm_90+).
__global__ void scatter_kernel(const int* __restrict__ src, const int* __restrict__ dst) {
    int gid = blockIdx.x * 256 + threadIdx.x;
    int e = gid >> 5, c = gid & 31;
    int s = __ldg(src + e), d = __ldg(dst + e);
    float4 v = *reinterpret_cast<const float4*>(g_xln + s * H_ + (c << 2));
    atomicAdd(reinterpret_cast<float4*>(g_agg + d * H_ + (c << 2)), v);
}

// ---------------------------------------------------------------------------
// Fused: y = (agg * deg_in^-0.5) @ Wg + bg ; 4 heads with softplus on stds.
// 8 rows per block (warp per row). Head weights staged transposed in smem.
// smem = (4*128*64 + 8*128 + 8*128)*4 = 139264 bytes.
// ---------------------------------------------------------------------------
__global__ void __launch_bounds__(256) final_kernel(
    const float* __restrict__ Wg,    const float* __restrict__ bg,
    const float* __restrict__ Wa_mu, const float* __restrict__ ba_mu,
    const float* __restrict__ Wa_sd, const float* __restrict__ ba_sd,
    const float* __restrict__ Wz_mu, const float* __restrict__ bz_mu,
    const float* __restrict__ Wz_sd, const float* __restrict__ bz_sd,
    float* __restrict__ out)
{
    extern __shared__ float fsm[];
    float* Wt = fsm;                 // [4][128][64] transposed head weights
    float* tb = fsm + 4 * 128 * 64;  // [8][128]
    float* yb = tb + 8 * 128;        // [8][128]

    // stage head weights transposed: Wt[head][k][i] = W[head][i][k]
    for (int idx = threadIdx.x; idx < 4 * I_ * H_; idx += 256) {
        int head = idx >> 13;
        int rem  = idx & 8191;
        int i    = rem >> 7;
        int k    = rem & 127;
        const float* W = head == 0 ? Wa_mu : head == 1 ? Wa_sd
                       : head == 2 ? Wz_mu : Wz_sd;
        Wt[(head << 13) + (k << 6) + i] = __ldg(W + rem);
    }

    int rw   = threadIdx.x >> 5;
    int lane = threadIdx.x & 31;
    int row  = (blockIdx.x << 3) + rw;

    // phase 1: t = agg * dst-norm
    {
        float dg = g_deg_in[row];
        float nd = dg > 0.f ? rsqrtf(dg) : 1.f;
        float4 v = *reinterpret_cast<const float4*>(g_agg + row * H_ + (lane << 2));
        v.x *= nd; v.y *= nd; v.z *= nd; v.w *= nd;
        *reinterpret_cast<float4*>(&tb[(rw << 7) + (lane << 2)]) = v;
    }
    __syncthreads();

    // phase 2: y = t @ Wg + bg   (Wg is (in,out): Wg[k*128 + j])
    float acc[4] = {0.f, 0.f, 0.f, 0.f};
    for (int k = 0; k < 128; ++k) {
        float tv = tb[(rw << 7) + k];
        #pragma unroll
        for (int q = 0; q < 4; ++q)
            acc[q] += tv * __ldg(Wg + (k << 7) + lane + (q << 5));
    }
    #pragma unroll
    for (int q = 0; q < 4; ++q)
        yb[(rw << 7) + lane + (q << 5)] = acc[q] + __ldg(bg + lane + (q << 5));
    __syncthreads();

    // phase 3: heads
    float ha0[2] = {0.f, 0.f}, ha1[2] = {0.f, 0.f};
    float hz0[2] = {0.f, 0.f}, hz1[2] = {0.f, 0.f};
    for (int k = 0; k < 128; ++k) {
        float yv = yb[(rw << 7) + k];
        int base = (k << 6) + lane;
        ha0[0] += yv * Wt[0 * 8192 + base];      ha0[1] += yv * Wt[0 * 8192 + base + 32];
        ha1[0] += yv * Wt[1 * 8192 + base];      ha1[1] += yv * Wt[1 * 8192 + base + 32];
        hz0[0] += yv * Wt[2 * 8192 + base];      hz0[1] += yv * Wt[2 * 8192 + base + 32];
        hz1[0] += yv * Wt[3 * 8192 + base];      hz1[1] += yv * Wt[3 * 8192 + base + 32];
    }
    // output order: zIG_mu | zIG_std | zIA_mu | zIA_std | h
    const int NI = N_ * I_;
    #pragma unroll
    for (int q = 0; q < 2; ++q) {
        int i = lane + (q << 5);
        out[2 * NI + row * I_ + i] = ha0[q] + __ldg(ba_mu + i);
        out[3 * NI + row * I_ + i] = softplusf(ha1[q] + __ldg(ba_sd + i));
        out[0      + row * I_ + i] = hz0[q] + __ldg(bz_mu + i);
        out[1 * NI + row * I_ + i] = softplusf(hz1[q] + __ldg(bz_sd + i));
    }
}

// ---------------------------------------------------------------------------
extern "C" void kernel_launch(void* const* d_in, const int* in_sizes, int n_in,
                              void* d_out, int out_size) {
    const float* actions = (const float*)d_in[0];
    const float* hidden  = (const float*)d_in[1];
    const int*   src     = (const int*)d_in[2];
    const int*   dst     = (const int*)d_in[3];
    const float* W_ih    = (const float*)d_in[4];
    const float* W_hh    = (const float*)d_in[5];
    const float* b_ih    = (const float*)d_in[6];
    const float* b_hh    = (const float*)d_in[7];
    const float* ln_g    = (const float*)d_in[8];
    const float* ln_b    = (const float*)d_in[9];
    const float* Wg      = (const float*)d_in[10];
    const float* bg      = (const float*)d_in[11];
    const float* Wa_mu   = (const float*)d_in[12];
    const float* ba_mu   = (const float*)d_in[13];
    const float* Wa_sd   = (const float*)d_in[14];
    const float* ba_sd   = (const float*)d_in[15];
    const float* Wz_mu   = (const float*)d_in[16];
    const float* bz_mu   = (const float*)d_in[17];
    const float* Wz_sd   = (const float*)d_in[18];
    const float* bz_sd   = (const float*)d_in[19];

    float* out   = (float*)d_out;
    float* h_out = out + 4 * N_ * I_;   // h region at tail

    const int GRU_SMEM = (K_ * G3_ + 16 * K_) * 4;             // 230400
    const int FIN_SMEM = (4 * I_ * H_ + 8 * H_ + 8 * H_) * 4;  // 139264
    cudaFuncSetAttribute(gru_kernel, cudaFuncAttributeMaxDynamicSharedMemorySize, GRU_SMEM);
    cudaFuncSetAttribute(final_kernel, cudaFuncAttributeMaxDynamicSharedMemorySize, FIN_SMEM);

    gru_kernel<<<N_ / 16, 256, GRU_SMEM>>>(actions, hidden, W_ih, W_hh, b_ih, b_hh, h_out);
    zero_deg_kernel<<<(N_ + 255) / 256, 256>>>();
    zero_agg_kernel<<<N_ * H_ / 4 / 256, 256>>>();
    degree_kernel<<<E_ / 256, 256>>>(src, dst);
    ln_scale_kernel<<<N_ / 8, 256>>>(h_out, ln_g, ln_b);
    scatter_kernel<<<E_ * 32 / 256, 256>>>(src, dst);
    final_kernel<<<N_ / 8, 256, FIN_SMEM>>>(Wg, bg, Wa_mu, ba_mu, Wa_sd, ba_sd,
                                            Wz_mu, bz_mu, Wz_sd, bz_sd, out);
}

// round 2
// speedup vs baseline: 1.0019x; 1.0019x over previous
#include <cuda_runtime.h>
#include <math.h>

#define N_  50000
#define T_  25
#define A_  16
#define H_  128
#define I_  64
#define E_  800000
#define G3_ 384   // 3*H
#define K_  144   // H + A

// Scratch (no allocations allowed): device globals.
__device__ float g_xln[N_ * H_];     // layernormed + src-norm-scaled features
__device__ float g_agg[N_ * H_];     // scatter-add accumulator
__device__ float g_deg_out[N_];
__device__ float g_deg_in[N_];

__device__ __forceinline__ float softplusf(float x) {
    return x > 0.f ? x + log1pf(expf(-x)) : log1pf(expf(x));
}

// ---------------------------------------------------------------------------
// GRU: 16 rows per block, all 25 steps in-block. W (transposed k-major) and the
// [h | x_t] tile live in smem. Thread tile: 4 rows x 2 cols x {r,z,hn,in}.
// smem = 144*384*4 + 16*144*4 = 230400 bytes.
// ---------------------------------------------------------------------------
__global__ void __launch_bounds__(256, 1) gru_kernel(
    const float* __restrict__ actions,  // (N, T, A)
    const float* __restrict__ hidden,   // (1, N, H)
    const float* __restrict__ W_ih,     // (3H, A)
    const float* __restrict__ W_hh,     // (3H, H)
    const float* __restrict__ b_ih,     // (3H)
    const float* __restrict__ b_hh,     // (3H)
    float* __restrict__ h_out)          // (N, H) -> d_out tail region
{
    extern __shared__ float sm[];
    float* Ws = sm;               // [K_][G3_]  (k-major transposed weights)
    float* hx = sm + K_ * G3_;    // [16][K_]   (h in cols 0..127, x in 128..143)

    const int tid   = threadIdx.x;
    const int rowg  = tid >> 6;        // 0..3  (constant within a warp)
    const int l2    = tid & 63;        // 0..63
    const int c0    = l2 << 1;         // column base, 0..126 (even)
    const int r0    = rowg << 2;       // local row base
    const int grow0 = blockIdx.x << 4; // global row base (16 rows/block)

    // Stage W_hh: [g][k] -> Ws[k][g], k in [0,128)
    for (int idx = tid; idx < G3_ * (H_ / 4); idx += 256) {
        int g  = idx >> 5;
        int k  = (idx & 31) << 2;
        float4 w = __ldg(reinterpret_cast<const float4*>(W_hh) + idx);
        Ws[(k + 0) * G3_ + g] = w.x;
        Ws[(k + 1) * G3_ + g] = w.y;
        Ws[(k + 2) * G3_ + g] = w.z;
        Ws[(k + 3) * G3_ + g] = w.w;
    }
    // Stage W_ih: [g][a] -> Ws[128+a][g]
    for (int idx = tid; idx < G3_ * (A_ / 4); idx += 256) {
        int g = idx >> 2;
        int k = 128 + ((idx & 3) << 2);
        float4 w = __ldg(reinterpret_cast<const float4*>(W_ih) + idx);
        Ws[(k + 0) * G3_ + g] = w.x;
        Ws[(k + 1) * G3_ + g] = w.y;
        Ws[(k + 2) * G3_ + g] = w.z;
        Ws[(k + 3) * G3_ + g] = w.w;
    }
    // Stage h0
    for (int idx = tid; idx < 16 * (H_ / 4); idx += 256) {
        int r  = idx >> 5;
        int k4 = idx & 31;
        float4 v = __ldg(reinterpret_cast<const float4*>(hidden + (grow0 + r) * H_) + k4);
        *reinterpret_cast<float4*>(&hx[r * K_ + (k4 << 2)]) = v;
    }
    // Biases for this thread's two columns (gate order r,z,n)
    float br0 = __ldg(b_ih + c0)       + __ldg(b_hh + c0);
    float br1 = __ldg(b_ih + c0 + 1)   + __ldg(b_hh + c0 + 1);
    float bz0 = __ldg(b_ih + 128 + c0)     + __ldg(b_hh + 128 + c0);
    float bz1 = __ldg(b_ih + 128 + c0 + 1) + __ldg(b_hh + 128 + c0 + 1);
    float bi0 = __ldg(b_ih + 256 + c0);
    float bi1 = __ldg(b_ih + 256 + c0 + 1);
    float bh0 = __ldg(b_hh + 256 + c0);
    float bh1 = __ldg(b_hh + 256 + c0 + 1);
    __syncthreads();

    const float* act_base = actions + (long long)grow0 * (T_ * A_);

    for (int t = 0; t < T_; ++t) {
        // load x_t tile (16 rows x 16) into hx[.][128..143]
        {
            int r = tid >> 4, a = tid & 15;
            hx[r * K_ + 128 + a] = __ldg(act_base + r * (T_ * A_) + t * A_ + a);
        }
        __syncthreads();

        float ar[4][2], az[4][2], ahn[4][2], ain[4][2];
        #pragma unroll
        for (int m = 0; m < 4; ++m) {
            ar[m][0] = br0;  ar[m][1] = br1;
            az[m][0] = bz0;  az[m][1] = bz1;
            ahn[m][0] = bh0; ahn[m][1] = bh1;
            ain[m][0] = bi0; ain[m][1] = bi1;
        }

        // recurrent part: k in [0,128)
        #pragma unroll 4
        for (int k = 0; k < 128; ++k) {
            float2 wr = *reinterpret_cast<const float2*>(&Ws[k * G3_ + c0]);
            float2 wz = *reinterpret_cast<const float2*>(&Ws[k * G3_ + 128 + c0]);
            float2 wn = *reinterpret_cast<const float2*>(&Ws[k * G3_ + 256 + c0]);
            #pragma unroll
            for (int m = 0; m < 4; ++m) {
                float h = hx[(r0 + m) * K_ + k];
                ar[m][0]  += h * wr.x;  ar[m][1]  += h * wr.y;
                az[m][0]  += h * wz.x;  az[m][1]  += h * wz.y;
                ahn[m][0] += h * wn.x;  ahn[m][1] += h * wn.y;
            }
        }
        // input part: k in [128,144) -> r,z merged; n goes to ain (separate!)
        #pragma unroll
        for (int k = 128; k < 144; ++k) {
            float2 wr = *reinterpret_cast<const float2*>(&Ws[k * G3_ + c0]);
            float2 wz = *reinterpret_cast<const float2*>(&Ws[k * G3_ + 128 + c0]);
            float2 wn = *reinterpret_cast<const float2*>(&Ws[k * G3_ + 256 + c0]);
            #pragma unroll
            for (int m = 0; m < 4; ++m) {
                float xv = hx[(r0 + m) * K_ + k];
                ar[m][0]  += xv * wr.x;  ar[m][1]  += xv * wr.y;
                az[m][0]  += xv * wz.x;  az[m][1]  += xv * wz.y;
                ain[m][0] += xv * wn.x;  ain[m][1] += xv * wn.y;
            }
        }

        // read h_old (before anyone overwrites), then sync, then write h_new
        float hold[4][2];
        #pragma unroll
        for (int m = 0; m < 4; ++m) {
            hold[m][0] = hx[(r0 + m) * K_ + c0];
            hold[m][1] = hx[(r0 + m) * K_ + c0 + 1];
        }
        __syncthreads();

        #pragma unroll
        for (int m = 0; m < 4; ++m) {
            #pragma unroll
            for (int jc = 0; jc < 2; ++jc) {
                float r = 1.f / (1.f + expf(-ar[m][jc]));
                float z = 1.f / (1.f + expf(-az[m][jc]));
                float n = tanhf(ain[m][jc] + r * ahn[m][jc]);
                float hnew = (1.f - z) * n + z * hold[m][jc];
                if (t == T_ - 1)
                    h_out[(grow0 + r0 + m) * H_ + c0 + jc] = hnew;
                else
                    hx[(r0 + m) * K_ + c0 + jc] = hnew;
            }
        }
        // next iteration's __syncthreads (after x load) orders hnew writes
    }
}

// ---------------------------------------------------------------------------
// LayerNorm + scale by src-norm (deg_out^-0.5). One warp per row.
// ---------------------------------------------------------------------------
__global__ void __launch_bounds__(256) ln_scale_kernel(
    const float* __restrict__ h, const float* __restrict__ ln_g,
    const float* __restrict__ ln_b)
{
    int row  = (blockIdx.x << 3) + (threadIdx.x >> 5);
    int lane = threadIdx.x & 31;
    float4 v = __ldg(reinterpret_cast<const float4*>(h + row * H_) + lane);
    float s  = v.x + v.y + v.z + v.w;
    float ss = v.x * v.x + v.y * v.y + v.z * v.z + v.w * v.w;
    #pragma unroll
    for (int o = 16; o > 0; o >>= 1) {
        s  += __shfl_xor_sync(0xffffffffu, s, o);
        ss += __shfl_xor_sync(0xffffffffu, ss, o);
    }
    float mu  = s * (1.f / 128.f);
    float var = ss * (1.f / 128.f) - mu * mu;
    float inv = rsqrtf(var + 1e-5f);
    float dg  = g_deg_out[row];
    float ns  = dg > 0.f ? rsqrtf(dg) : 1.f;
    float4 g4 = __ldg(reinterpret_cast<const float4*>(ln_g) + lane);
    float4 b4 = __ldg(reinterpret_cast<const float4*>(ln_b) + lane);
    float4 o4;
    o4.x = ((v.x - mu) * inv * g4.x + b4.x) * ns;
    o4.y = ((v.y - mu) * inv * g4.y + b4.y) * ns;
    o4.z = ((v.z - mu) * inv * g4.z + b4.z) * ns;
    o4.w = ((v.w - mu) * inv * g4.w + b4.w) * ns;
    *reinterpret_cast<float4*>(g_xln + row * H_ + (lane << 2)) = o4;
}

__global__ void zero_deg_kernel() {
    int i = blockIdx.x * 256 + threadIdx.x;
    if (i < N_) { g_deg_in[i] = 0.f; g_deg_out[i] = 0.f; }
}

__global__ void zero_agg_kernel() {
    int i = blockIdx.x * 256 + threadIdx.x;   // N_*H_/4 = 1,600,000 exact
    reinterpret_cast<float4*>(g_agg)[i] = make_float4(0.f, 0.f, 0.f, 0.f);
}

__global__ void degree_kernel(const int* __restrict__ src, const int* __restrict__ dst) {
    int e = blockIdx.x * 256 + threadIdx.x;   // grid exact: E_/256
    atomicAdd(&g_deg_out[__ldg(src + e)], 1.f);
    atomicAdd(&g_deg_in[__ldg(dst + e)], 1.f);
}

// One warp per edge; lane handles a float4 column chunk. float4 atomics (sm_90+).
__global__ void scatter_kernel(const int* __restrict__ src, const int* __restrict__ dst) {
    int gid = blockIdx.x * 256 + threadIdx.x;
    int e = gid >> 5, c = gid & 31;
    int s = __ldg(src + e), d = __ldg(dst + e);
    float4 v = *reinterpret_cast<const float4*>(g_xln + s * H_ + (c << 2));
    atomicAdd(reinterpret_cast<float4*>(g_agg + d * H_ + (c << 2)), v);
}

// ---------------------------------------------------------------------------
// Fused: y = (agg * deg_in^-0.5) @ Wg + bg ; 4 heads with softplus on stds.
// 8 rows per block (warp per row). Head weights staged transposed in smem.
// smem = (4*128*64 + 8*128 + 8*128)*4 = 139264 bytes.
// ---------------------------------------------------------------------------
__global__ void __launch_bounds__(256) final_kernel(
    const float* __restrict__ Wg,    const float* __restrict__ bg,
    const float* __restrict__ Wa_mu, const float* __restrict__ ba_mu,
    const float* __restrict__ Wa_sd, const float* __restrict__ ba_sd,
    const float* __restrict__ Wz_mu, const float* __restrict__ bz_mu,
    const float* __restrict__ Wz_sd, const float* __restrict__ bz_sd,
    float* __restrict__ out)
{
    extern __shared__ float fsm[];
    float* Wt = fsm;                 // [4][128][64] transposed head weights
    float* tb = fsm + 4 * 128 * 64;  // [8][128]
    float* yb = tb + 8 * 128;        // [8][128]

    // stage head weights transposed: Wt[head][k][i] = W[head][i][k]
    for (int idx = threadIdx.x; idx < 4 * I_ * H_; idx += 256) {
        int head = idx >> 13;
        int rem  = idx & 8191;
        int i    = rem >> 7;
        int k    = rem & 127;
        const float* W = head == 0 ? Wa_mu : head == 1 ? Wa_sd
                       : head == 2 ? Wz_mu : Wz_sd;
        Wt[(head << 13) + (k << 6) + i] = __ldg(W + rem);
    }

    int rw   = threadIdx.x >> 5;
    int lane = threadIdx.x & 31;
    int row  = (blockIdx.x << 3) + rw;

    // phase 1: t = agg * dst-norm
    {
        float dg = g_deg_in[row];
        float nd = dg > 0.f ? rsqrtf(dg) : 1.f;
        float4 v = *reinterpret_cast<const float4*>(g_agg + row * H_ + (lane << 2));
        v.x *= nd; v.y *= nd; v.z *= nd; v.w *= nd;
        *reinterpret_cast<float4*>(&tb[(rw << 7) + (lane << 2)]) = v;
    }
    __syncthreads();

    // phase 2: y = t @ Wg + bg   (Wg is (in,out): Wg[k*128 + j])
    float acc[4] = {0.f, 0.f, 0.f, 0.f};
    for (int k = 0; k < 128; ++k) {
        float tv = tb[(rw << 7) + k];
        #pragma unroll
        for (int q = 0; q < 4; ++q)
            acc[q] += tv * __ldg(Wg + (k << 7) + lane + (q << 5));
    }
    #pragma unroll
    for (int q = 0; q < 4; ++q)
        yb[(rw << 7) + lane + (q << 5)] = acc[q] + __ldg(bg + lane + (q << 5));
    __syncthreads();

    // phase 3: heads
    float ha0[2] = {0.f, 0.f}, ha1[2] = {0.f, 0.f};
    float hz0[2] = {0.f, 0.f}, hz1[2] = {0.f, 0.f};
    for (int k = 0; k < 128; ++k) {
        float yv = yb[(rw << 7) + k];
        int base = (k << 6) + lane;
        ha0[0] += yv * Wt[0 * 8192 + base];      ha0[1] += yv * Wt[0 * 8192 + base + 32];
        ha1[0] += yv * Wt[1 * 8192 + base];      ha1[1] += yv * Wt[1 * 8192 + base + 32];
        hz0[0] += yv * Wt[2 * 8192 + base];      hz0[1] += yv * Wt[2 * 8192 + base + 32];
        hz1[0] += yv * Wt[3 * 8192 + base];      hz1[1] += yv * Wt[3 * 8192 + base + 32];
    }
    // output order: zIG_mu | zIG_std | zIA_mu | zIA_std | h
    const int NI = N_ * I_;
    #pragma unroll
    for (int q = 0; q < 2; ++q) {
        int i = lane + (q << 5);
        out[2 * NI + row * I_ + i] = ha0[q] + __ldg(ba_mu + i);
        out[3 * NI + row * I_ + i] = softplusf(ha1[q] + __ldg(ba_sd + i));
        out[0      + row * I_ + i] = hz0[q] + __ldg(bz_mu + i);
        out[1 * NI + row * I_ + i] = softplusf(hz1[q] + __ldg(bz_sd + i));
    }
}

// ---------------------------------------------------------------------------
extern "C" void kernel_launch(void* const* d_in, const int* in_sizes, int n_in,
                              void* d_out, int out_size) {
    const float* actions = (const float*)d_in[0];
    const float* hidden  = (const float*)d_in[1];
    const int*   src     = (const int*)d_in[2];
    const int*   dst     = (const int*)d_in[3];
    const float* W_ih    = (const float*)d_in[4];
    const float* W_hh    = (const float*)d_in[5];
    const float* b_ih    = (const float*)d_in[6];
    const float* b_hh    = (const float*)d_in[7];
    const float* ln_g    = (const float*)d_in[8];
    const float* ln_b    = (const float*)d_in[9];
    const float* Wg      = (const float*)d_in[10];
    const float* bg      = (const float*)d_in[11];
    const float* Wa_mu   = (const float*)d_in[12];
    const float* ba_mu   = (const float*)d_in[13];
    const float* Wa_sd   = (const float*)d_in[14];
    const float* ba_sd   = (const float*)d_in[15];
    const float* Wz_mu   = (const float*)d_in[16];
    const float* bz_mu   = (const float*)d_in[17];
    const float* Wz_sd   = (const float*)d_in[18];
    const float* bz_sd   = (const float*)d_in[19];

    float* out   = (float*)d_out;
    float* h_out = out + 4 * N_ * I_;   // h region at tail

    const int GRU_SMEM = (K_ * G3_ + 16 * K_) * 4;             // 230400
    const int FIN_SMEM = (4 * I_ * H_ + 8 * H_ + 8 * H_) * 4;  // 139264
    cudaFuncSetAttribute(gru_kernel, cudaFuncAttributeMaxDynamicSharedMemorySize, GRU_SMEM);
    cudaFuncSetAttribute(final_kernel, cudaFuncAttributeMaxDynamicSharedMemorySize, FIN_SMEM);

    gru_kernel<<<N_ / 16, 256, GRU_SMEM>>>(actions, hidden, W_ih, W_hh, b_ih, b_hh, h_out);
    zero_deg_kernel<<<(N_ + 255) / 256, 256>>>();
    zero_agg_kernel<<<N_ * H_ / 4 / 256, 256>>>();
    degree_kernel<<<E_ / 256, 256>>>(src, dst);
    ln_scale_kernel<<<N_ / 8, 256>>>(h_out, ln_g, ln_b);
    scatter_kernel<<<E_ * 32 / 256, 256>>>(src, dst);
    final_kernel<<<N_ / 8, 256, FIN_SMEM>>>(Wg, bg, Wa_mu, ba_mu, Wa_sd, ba_sd,
                                            Wz_mu, bz_mu, Wz_sd, bz_sd, out);
}